// round 12
// baseline (speedup 1.0000x reference)
#include <cuda_runtime.h>
#include <stdint.h>

#define NDIM   64
#define BATCH  262144
#define ALPHA  0.05f
#define BETA   0.9975f          /* 1 - ALPHA^2 */
#define MAXIT  200
#define TOL2   1.0e-4f          /* TOL^2 */
#define TPB    128
#define NBLK   (BATCH / TPB)
#define CKPT   8                /* checkpoint spacing (MAXIT % CKPT == 0) */
#define NGRP   (MAXIT / CKPT)   /* 25 */
#define NBKT   (NGRP + 1)       /* buckets over kbr: 8,16,...,200,201 -> 26 */
#define ROWS_PER_LANE (BATCH / 32)   /* 8192 rows per lane-sharded pool */

/* persistent scratch (module-static, not runtime alloc) */
__device__ float g_tsave[BATCH * NDIM];   /* 64 MB: t-state at saved iteration       */
__device__ float g_negh[BATCH];           /* -h at saved iteration                   */
__device__ float g_st[BATCH];             /* sum(t) at saved iteration               */
__device__ int   g_ks[BATCH];             /* iteration index of saved state          */
__device__ int   g_kbr[BATCH];            /* bracket upper: first converged ckpt, or 201 */
__device__ int   g_perm[BATCH];           /* rows sorted by bucket (ks)              */
__device__ int   g_hist[NBKT];            /* bucket histogram                        */
__device__ int   g_boff[NBKT];            /* bucket scatter offsets                  */
__device__ int   g_ctr[32];               /* lane-sharded row counters               */
__device__ int   g_ctl[2];                /* [0]=K_cand (max kbr), [1]=exact K       */

/* one SASS FADD.SAT: clamp(a+b, 0, 1) */
__device__ __forceinline__ float add_sat01(float a, float b) {
    float r; asm("add.rn.sat.f32 %0, %1, %2;" : "=f"(r) : "f"(a), "f"(b)); return r;
}

__device__ __forceinline__ unsigned rotl32(unsigned x, int r) {
    return (x << r) | (x >> (32 - r));
}

/* Threefry-2x32, key=(0,1); partitionable counter mode; draw = x0 ^ x1. */
__device__ __forceinline__ float rng_u01(unsigned i)
{
    unsigned x0 = 0u, x1 = i;
    const unsigned ks0 = 0u, ks1 = 1u, ks2 = 0x1BD11BDBu;
    x0 += ks0; x1 += ks1;
#define TF_R(r) { x0 += x1; x1 = rotl32(x1, (r)); x1 ^= x0; }
    TF_R(13) TF_R(15) TF_R(26) TF_R(6)
    x0 += ks1; x1 += ks2 + 1u;
    TF_R(17) TF_R(29) TF_R(16) TF_R(24)
    x0 += ks2; x1 += ks0 + 2u;
    TF_R(13) TF_R(15) TF_R(26) TF_R(6)
    x0 += ks0; x1 += ks1 + 3u;
    TF_R(17) TF_R(29) TF_R(16) TF_R(24)
    x0 += ks1; x1 += ks2 + 4u;
    TF_R(13) TF_R(15) TF_R(26) TF_R(6)
    x0 += ks2; x1 += ks0 + 5u;
#undef TF_R
    unsigned b = x0 ^ x1;
    float f = __uint_as_float((b >> 9) | 0x3f800000u) - 1.0f;
    return fmaxf(f, 0.0f);
}

/* ---- one cheap DYS iteration (no convergence statistic) ---- */
__device__ __forceinline__ void cheap_iter(float* t, const float* nac,
    float& st, float& negh, float snac, float A0, float bs, float gg)
{
    float sx0 = 0.f, sx1 = 0.f, sx2 = 0.f, sx3 = 0.f;
#pragma unroll
    for (int j = 0; j < NDIM; j += 4) {
        float xa = add_sat01(t[j+0], negh);
        float xb = add_sat01(t[j+1], negh);
        float xc = add_sat01(t[j+2], negh);
        float xd = add_sat01(t[j+3], negh);
        sx0 += xa; sx1 += xb; sx2 += xc; sx3 += xd;
        t[j+0] = fmaf(xa, BETA, nac[j+0]);
        t[j+1] = fmaf(xb, BETA, nac[j+1]);
        t[j+2] = fmaf(xc, BETA, nac[j+2]);
        t[j+3] = fmaf(xd, BETA, nac[j+3]);
    }
    float sx = (sx0 + sx1) + (sx2 + sx3);
    float st_new = fmaf(BETA, sx, snac);
    float s  = sx + st_new - st - 64.0f * negh;
    float h  = fmaf(A0, s, -bs) * gg;
    st = st_new;
    negh = -h;
}

/* ---- one instrumented DYS iteration: returns d^2 ---- */
__device__ __forceinline__ float inst_iter(float* t, const float* nac,
    float& st, float& negh, float snac, float A0, float bs, float gg)
{
    float sx0 = 0.f, sx1 = 0.f, sx2 = 0.f, sx3 = 0.f;
    float q0 = 0.f, q1 = 0.f, q2v = 0.f, q3 = 0.f;
#pragma unroll
    for (int j = 0; j < NDIM; j += 4) {
        float xa = add_sat01(t[j+0], negh);
        float xb = add_sat01(t[j+1], negh);
        float xc = add_sat01(t[j+2], negh);
        float xd = add_sat01(t[j+3], negh);
        sx0 += xa; sx1 += xb; sx2 += xc; sx3 += xd;
        float ta = fmaf(xa, BETA, nac[j+0]);
        float tb = fmaf(xb, BETA, nac[j+1]);
        float tc = fmaf(xc, BETA, nac[j+2]);
        float td = fmaf(xd, BETA, nac[j+3]);
        float da = ta - t[j+0], db = tb - t[j+1];
        float dc = tc - t[j+2], dd = td - t[j+3];
        q0 = fmaf(da, da, q0); q1 = fmaf(db, db, q1);
        q2v = fmaf(dc, dc, q2v); q3 = fmaf(dd, dd, q3);
        t[j+0] = ta; t[j+1] = tb; t[j+2] = tc; t[j+3] = td;
    }
    float sx = (sx0 + sx1) + (sx2 + sx3);
    float qq = (q0 + q1) + (q2v + q3);

    float st_new = fmaf(BETA, sx, snac);
    float s  = sx + st_new - st - 64.0f * negh;
    float h  = fmaf(A0, s, -bs) * gg;
    float sd = st_new - st;
    float D  = -h - negh;
    float d2 = fmaf(64.0f * D, D, fmaf(2.0f * D, sd, qq));
    st = st_new;
    negh = -h;
    return d2;
}

__device__ __forceinline__ void load_nac(const float* cost, int row,
                                         float* nac, float& snac)
{
    snac = 0.0f;
    const float4* c4 = (const float4*)(cost + (size_t)row * NDIM);
#pragma unroll
    for (int q = 0; q < NDIM / 4; q++) {
        float4 v = c4[q];
        nac[4*q+0] = -ALPHA * v.x;
        nac[4*q+1] = -ALPHA * v.y;
        nac[4*q+2] = -ALPHA * v.z;
        nac[4*q+3] = -ALPHA * v.w;
        snac += nac[4*q+0] + nac[4*q+1] + nac[4*q+2] + nac[4*q+3];
    }
}

/* ---------------- Pass 1: persistent, lane-level work stealing --------------
   Each lane draws rows from its own sharded counter (no atomic contention,
   near-perfect load balance). Lanes stay group-phase aligned (k % 8 == 0 at
   boundaries) so the checkpoint + instrumented-d2 path remains warp-uniform.
   Per-row math is instruction-identical to the fixed-assignment version.     */
__global__ void __launch_bounds__(TPB)
dys_pass1(const float* __restrict__ cost,
          const float* __restrict__ Avec,
          const float* __restrict__ bvec,
          const float* __restrict__ Vvec,
          const float* __restrict__ UT,
          const float* __restrict__ s_inv)
{
    __shared__ float4 sbuf[TPB * 16];     /* 32 KB: per-thread checkpoint state */
    const int tid  = threadIdx.x;
    const int lane = tid & 31;

    const float bs = bvec[0];
    const float A0 = Avec[0];
    const float gg = UT[0] * s_inv[0] * Vvec[0];

    float t[NDIM], nac[NDIM];
    float snac = 0.f, st = 0.f, negh = 0.f, nck = 0.f, stck = 0.f;
    int   row = -1, k = 0, mykmax = 0;
    bool  alive = true, need_new = true;

    for (;;) {
        /* ---- group boundary: recycle finished lanes ---- */
        if (alive && need_new) {
            int idx = atomicAdd(&g_ctr[lane], 1);
            if (idx >= ROWS_PER_LANE) {
                alive = false;
            } else {
                row = idx * 32 + lane;
                load_nac(cost, row, nac, snac);
                st = 0.0f;
#pragma unroll
                for (int j = 0; j < NDIM; j++) {
                    t[j] = rng_u01((unsigned)(row * NDIM + j));
                    st += t[j];
                }
                negh = 0.0f;
                k = 0;
            }
            need_new = false;
        }
        if (__ballot_sync(0xffffffffu, alive) == 0u) break;

        /* ---- checkpoint state at group entry (k multiple of 8) ---- */
        if (alive) {
#pragma unroll
            for (int s2 = 0; s2 < 16; s2++) {
                int idx = (tid << 4) + ((s2 + tid) & 15);
                sbuf[idx] = make_float4(t[4*s2+0], t[4*s2+1], t[4*s2+2], t[4*s2+3]);
            }
            nck = negh; stck = st;
        }

        /* ---- 8 iterations (dead lanes compute garbage in regs; harmless) */
#pragma unroll 1
        for (int j = 0; j < CKPT - 1; j++)
            cheap_iter(t, nac, st, negh, snac, A0, bs, gg);
        float d2 = inst_iter(t, nac, st, negh, snac, A0, bs, gg);

        if (alive) {
            k += CKPT;
            bool conv = (d2 <= TOL2);
            if (conv || k >= MAXIT) {
                int kbr = conv ? k : (MAXIT + 1);
                mykmax = max(mykmax, kbr);
                float4* ts4 = (float4*)(g_tsave + (size_t)row * NDIM);
                if (conv) {
                    /* save state at kbr - 8 from the smem checkpoint */
#pragma unroll
                    for (int s2 = 0; s2 < 16; s2++)
                        ts4[s2] = sbuf[(tid << 4) + ((s2 + tid) & 15)];
                    g_negh[row] = nck;
                    g_st[row]   = stck;
                    g_ks[row]   = k - CKPT;
                } else {
                    /* never converged: save state at 200 */
#pragma unroll
                    for (int s2 = 0; s2 < 16; s2++)
                        ts4[s2] = make_float4(t[4*s2+0], t[4*s2+1],
                                              t[4*s2+2], t[4*s2+3]);
                    g_negh[row] = negh;
                    g_st[row]   = st;
                    g_ks[row]   = MAXIT;
                }
                g_kbr[row] = kbr;
                need_new = true;
            }
        }
    }

    /* one atomic per warp for the global bracket max */
    int wmax = __reduce_max_sync(0xffffffffu, mykmax);
    if (lane == 0) atomicMax(&g_ctl[0], wmax);
}

/* ------------- Refine: exact K from rows in the top bracket ----------------- */
__global__ void __launch_bounds__(TPB)
dys_refine(const float* __restrict__ cost,
           const float* __restrict__ Avec,
           const float* __restrict__ bvec,
           const float* __restrict__ Vvec,
           const float* __restrict__ UT,
           const float* __restrict__ s_inv)
{
    const int row = blockIdx.x * TPB + threadIdx.x;
    const int Kc  = g_ctl[0];

    if (Kc > MAXIT) {                     /* some row never converged -> cap  */
        if (row == 0) g_ctl[1] = MAXIT;
        return;
    }
    if (g_kbr[row] != Kc) return;         /* only top-bracket rows refine     */

    const float bs = bvec[0];
    const float A0 = Avec[0];
    const float gg = UT[0] * s_inv[0] * Vvec[0];

    float t[NDIM], nac[NDIM], snac;
    load_nac(cost, row, nac, snac);

    const float4* ts4 = (const float4*)(g_tsave + (size_t)row * NDIM);
#pragma unroll
    for (int q = 0; q < NDIM / 4; q++) {
        float4 v = ts4[q];
        t[4*q+0] = v.x; t[4*q+1] = v.y; t[4*q+2] = v.z; t[4*q+3] = v.w;
    }
    float negh = g_negh[row];
    float st   = g_st[row];
    const int ks = g_ks[row];             /* = Kc - CKPT                      */

    int kx = Kc;
#pragma unroll 1
    for (int j = 1; j <= CKPT; j++) {
        float d2 = inst_iter(t, nac, st, negh, snac, A0, bs, gg);
        if (d2 <= TOL2) { kx = ks + j; break; }   /* guaranteed by j=CKPT     */
    }
    atomicMax(&g_ctl[1], kx);
}

/* ------------- Histogram (block-aggregated) --------------------------------- */
__global__ void __launch_bounds__(256)
dys_hist()
{
    __shared__ int sh_cnt[NBKT];
    const int tid = threadIdx.x;
    const int row = blockIdx.x * 256 + tid;

    if (tid < NBKT) sh_cnt[tid] = 0;
    __syncthreads();

    int kbr = g_kbr[row];
    int bkt = (kbr <= MAXIT) ? (kbr / CKPT - 1) : (NBKT - 1);
    atomicAdd(&sh_cnt[bkt], 1);
    __syncthreads();

    if (tid < NBKT) {
        int c = sh_cnt[tid];
        if (c > 0) atomicAdd(&g_hist[tid], c);
    }
}

/* ------------- Prefix: warp-parallel exclusive scan over 26 buckets --------- */
__global__ void dys_prefix()
{
    const int i = threadIdx.x;            /* 32 threads */
    int v = (i < NBKT) ? g_hist[i] : 0;
    int s = v;
#pragma unroll
    for (int off = 1; off < 32; off <<= 1) {
        int n = __shfl_up_sync(0xffffffffu, s, off);
        if (i >= off) s += n;
    }
    if (i < NBKT) g_boff[i] = s - v;      /* exclusive prefix */
}

/* ------------- Scatter: per-block aggregation, low-contention atomics ------- */
__global__ void __launch_bounds__(256)
dys_scatter()
{
    __shared__ int sh_cnt[NBKT];
    __shared__ int sh_base[NBKT];
    const int tid = threadIdx.x;
    const int row = blockIdx.x * 256 + tid;

    if (tid < NBKT) sh_cnt[tid] = 0;
    __syncthreads();

    int kbr = g_kbr[row];
    int bkt = (kbr <= MAXIT) ? (kbr / CKPT - 1) : (NBKT - 1);
    int lrank = atomicAdd(&sh_cnt[bkt], 1);
    __syncthreads();

    if (tid < NBKT) {
        int c = sh_cnt[tid];
        sh_base[tid] = (c > 0) ? atomicAdd(&g_boff[tid], c) : 0;
    }
    __syncthreads();

    g_perm[sh_base[bkt] + lrank] = row;
}

/* ---------------- Pass 2: catch up to exact K, final step, output ----------- */
__global__ void __launch_bounds__(TPB)
dys_pass2(const float* __restrict__ cost,
          const float* __restrict__ Avec,
          const float* __restrict__ bvec,
          const float* __restrict__ Vvec,
          const float* __restrict__ UT,
          const float* __restrict__ s_inv,
          float* __restrict__ out)
{
    const int slot = blockIdx.x * TPB + threadIdx.x;
    const int row  = g_perm[slot];        /* lanes share a ks bucket -> no divergence */

    const float bs = bvec[0];
    const float A0 = Avec[0];
    const float gg = UT[0] * s_inv[0] * Vvec[0];

    float t[NDIM], nac[NDIM], snac;
    load_nac(cost, row, nac, snac);

    const float4* ts4 = (const float4*)(g_tsave + (size_t)row * NDIM);
#pragma unroll
    for (int q = 0; q < NDIM / 4; q++) {
        float4 v = ts4[q];
        t[4*q+0] = v.x; t[4*q+1] = v.y; t[4*q+2] = v.z; t[4*q+3] = v.w;
    }
    float negh = g_negh[row];
    float st   = g_st[row];
    const int ks = g_ks[row];
    const int K  = g_ctl[1];

#pragma unroll 1
    for (int k = ks; k < K; k++)
        cheap_iter(t, nac, st, negh, snac, A0, bs, gg);

    /* one final (differentiable) DYS step; sol = clip(t_new - h, 0, 1) */
    {
        float sx0 = 0.f, sx1 = 0.f, sx2 = 0.f, sx3 = 0.f;
#pragma unroll
        for (int j = 0; j < NDIM; j += 4) {
            float xa = add_sat01(t[j+0], negh);
            float xb = add_sat01(t[j+1], negh);
            float xc = add_sat01(t[j+2], negh);
            float xd = add_sat01(t[j+3], negh);
            sx0 += xa; sx1 += xb; sx2 += xc; sx3 += xd;
            t[j+0] = fmaf(xa, BETA, nac[j+0]);
            t[j+1] = fmaf(xb, BETA, nac[j+1]);
            t[j+2] = fmaf(xc, BETA, nac[j+2]);
            t[j+3] = fmaf(xd, BETA, nac[j+3]);
        }
        float sx = (sx0 + sx1) + (sx2 + sx3);
        float st_new = fmaf(BETA, sx, snac);
        float s  = sx + st_new - st - 64.0f * negh;
        float h  = fmaf(A0, s, -bs) * gg;
        float nh = -h;

        float4* o4 = (float4*)(out + (size_t)row * NDIM);
#pragma unroll
        for (int q = 0; q < NDIM / 4; q++) {
            float4 v;
            v.x = add_sat01(t[4*q+0], nh);
            v.y = add_sat01(t[4*q+1], nh);
            v.z = add_sat01(t[4*q+2], nh);
            v.w = add_sat01(t[4*q+3], nh);
            o4[q] = v;
        }
    }
}

extern "C" void kernel_launch(void* const* d_in, const int* in_sizes, int n_in,
                              void* d_out, int out_size)
{
    const float* cost  = (const float*)d_in[0];
    const float* A     = (const float*)d_in[1];
    const float* b     = (const float*)d_in[2];
    /* d_in[3] = lb (zeros), d_in[4] = ub (ones): folded into .sat clamp */
    const float* V     = (const float*)d_in[5];
    const float* UT    = (const float*)d_in[6];
    const float* s_inv = (const float*)d_in[7];
    float* out = (float*)d_out;

    void* ctlAddr = nullptr;
    cudaGetSymbolAddress(&ctlAddr, g_ctl);
    cudaMemsetAsync(ctlAddr, 0, 2 * sizeof(int));
    void* histAddr = nullptr;
    cudaGetSymbolAddress(&histAddr, g_hist);
    cudaMemsetAsync(histAddr, 0, NBKT * sizeof(int));
    void* ctrAddr = nullptr;
    cudaGetSymbolAddress(&ctrAddr, g_ctr);
    cudaMemsetAsync(ctrAddr, 0, 32 * sizeof(int));

    int dev = 0;
    cudaGetDevice(&dev);
    int sms = 0;
    cudaDeviceGetAttribute(&sms, cudaDevAttrMultiProcessorCount, dev);
    int bpm = 0;
    cudaOccupancyMaxActiveBlocksPerMultiprocessor(&bpm, dys_pass1, TPB, 0);
    if (bpm < 1) bpm = 1;
    int p1blocks = sms * bpm;             /* persistent: one co-resident wave */

    dys_pass1  <<<p1blocks, TPB>>>(cost, A, b, V, UT, s_inv);
    dys_refine <<<NBLK, TPB>>>(cost, A, b, V, UT, s_inv);
    dys_hist   <<<BATCH / 256, 256>>>();
    dys_prefix <<<1, 32>>>();
    dys_scatter<<<BATCH / 256, 256>>>();
    dys_pass2  <<<NBLK, TPB>>>(cost, A, b, V, UT, s_inv, out);
}

// round 13
// speedup vs baseline: 3.9187x; 3.9187x over previous
#include <cuda_runtime.h>
#include <stdint.h>

#define NDIM   64
#define BATCH  262144
#define ALPHA  0.05f
#define BETA   0.9975f          /* 1 - ALPHA^2 */
#define MAXIT  200
#define TOL2   1.0e-4f          /* TOL^2 */
#define TPB    128
#define NBLK   (BATCH / TPB)
#define CKPT   8                /* checkpoint spacing (MAXIT % CKPT == 0) */
#define NGRP   (MAXIT / CKPT)   /* 25 */
#define NBKT   (NGRP + 1)       /* buckets over kbr: 8,16,...,200,201 -> 26 */

/* persistent scratch (module-static, not runtime alloc) */
__device__ float g_tsave[BATCH * NDIM];   /* 64 MB: t-state at saved iteration       */
__device__ float g_negh[BATCH];           /* -h at saved iteration                   */
__device__ float g_st[BATCH];             /* sum(t) at saved iteration               */
__device__ int   g_ks[BATCH];             /* iteration index of saved state          */
__device__ int   g_kbr[BATCH];            /* bracket upper: first converged ckpt, or 201 */
__device__ int   g_perm[BATCH];           /* rows sorted by bucket (ks)              */
__device__ int   g_hist[NBKT];            /* bucket histogram                        */
__device__ int   g_boff[NBKT];            /* bucket scatter offsets                  */
__device__ int   g_ctl[2];                /* [0]=K_cand (max kbr), [1]=exact K       */

/* one SASS FADD.SAT: clamp(a+b, 0, 1) */
__device__ __forceinline__ float add_sat01(float a, float b) {
    float r; asm("add.rn.sat.f32 %0, %1, %2;" : "=f"(r) : "f"(a), "f"(b)); return r;
}

__device__ __forceinline__ unsigned rotl32(unsigned x, int r) {
    return (x << r) | (x >> (32 - r));
}

/* Threefry-2x32, key=(0,1); partitionable counter mode; draw = x0 ^ x1. */
__device__ __forceinline__ float rng_u01(unsigned i)
{
    unsigned x0 = 0u, x1 = i;
    const unsigned ks0 = 0u, ks1 = 1u, ks2 = 0x1BD11BDBu;
    x0 += ks0; x1 += ks1;
#define TF_R(r) { x0 += x1; x1 = rotl32(x1, (r)); x1 ^= x0; }
    TF_R(13) TF_R(15) TF_R(26) TF_R(6)
    x0 += ks1; x1 += ks2 + 1u;
    TF_R(17) TF_R(29) TF_R(16) TF_R(24)
    x0 += ks2; x1 += ks0 + 2u;
    TF_R(13) TF_R(15) TF_R(26) TF_R(6)
    x0 += ks0; x1 += ks1 + 3u;
    TF_R(17) TF_R(29) TF_R(16) TF_R(24)
    x0 += ks1; x1 += ks2 + 4u;
    TF_R(13) TF_R(15) TF_R(26) TF_R(6)
    x0 += ks2; x1 += ks0 + 5u;
#undef TF_R
    unsigned b = x0 ^ x1;
    float f = __uint_as_float((b >> 9) | 0x3f800000u) - 1.0f;
    return fmaxf(f, 0.0f);
}

/* ---- one cheap DYS iteration (no convergence statistic) ---- */
__device__ __forceinline__ void cheap_iter(float* t, const float* nac,
    float& st, float& negh, float snac, float A0, float bs, float gg)
{
    float sx0 = 0.f, sx1 = 0.f, sx2 = 0.f, sx3 = 0.f;
#pragma unroll
    for (int j = 0; j < NDIM; j += 4) {
        float xa = add_sat01(t[j+0], negh);
        float xb = add_sat01(t[j+1], negh);
        float xc = add_sat01(t[j+2], negh);
        float xd = add_sat01(t[j+3], negh);
        sx0 += xa; sx1 += xb; sx2 += xc; sx3 += xd;
        t[j+0] = fmaf(xa, BETA, nac[j+0]);
        t[j+1] = fmaf(xb, BETA, nac[j+1]);
        t[j+2] = fmaf(xc, BETA, nac[j+2]);
        t[j+3] = fmaf(xd, BETA, nac[j+3]);
    }
    float sx = (sx0 + sx1) + (sx2 + sx3);
    float st_new = fmaf(BETA, sx, snac);
    float s  = sx + st_new - st - 64.0f * negh;
    float h  = fmaf(A0, s, -bs) * gg;
    st = st_new;
    negh = -h;
}

/* ---- one instrumented DYS iteration: returns d^2 ---- */
__device__ __forceinline__ float inst_iter(float* t, const float* nac,
    float& st, float& negh, float snac, float A0, float bs, float gg)
{
    float sx0 = 0.f, sx1 = 0.f, sx2 = 0.f, sx3 = 0.f;
    float q0 = 0.f, q1 = 0.f, q2v = 0.f, q3 = 0.f;
#pragma unroll
    for (int j = 0; j < NDIM; j += 4) {
        float xa = add_sat01(t[j+0], negh);
        float xb = add_sat01(t[j+1], negh);
        float xc = add_sat01(t[j+2], negh);
        float xd = add_sat01(t[j+3], negh);
        sx0 += xa; sx1 += xb; sx2 += xc; sx3 += xd;
        float ta = fmaf(xa, BETA, nac[j+0]);
        float tb = fmaf(xb, BETA, nac[j+1]);
        float tc = fmaf(xc, BETA, nac[j+2]);
        float td = fmaf(xd, BETA, nac[j+3]);
        float da = ta - t[j+0], db = tb - t[j+1];
        float dc = tc - t[j+2], dd = td - t[j+3];
        q0 = fmaf(da, da, q0); q1 = fmaf(db, db, q1);
        q2v = fmaf(dc, dc, q2v); q3 = fmaf(dd, dd, q3);
        t[j+0] = ta; t[j+1] = tb; t[j+2] = tc; t[j+3] = td;
    }
    float sx = (sx0 + sx1) + (sx2 + sx3);
    float qq = (q0 + q1) + (q2v + q3);

    float st_new = fmaf(BETA, sx, snac);
    float s  = sx + st_new - st - 64.0f * negh;
    float h  = fmaf(A0, s, -bs) * gg;
    float sd = st_new - st;
    float D  = -h - negh;
    float d2 = fmaf(64.0f * D, D, fmaf(2.0f * D, sd, qq));
    st = st_new;
    negh = -h;
    return d2;
}

__device__ __forceinline__ void load_nac(const float* cost, int row,
                                         float* nac, float& snac)
{
    snac = 0.0f;
    const float4* c4 = (const float4*)(cost + (size_t)row * NDIM);
#pragma unroll
    for (int q = 0; q < NDIM / 4; q++) {
        float4 v = c4[q];
        nac[4*q+0] = -ALPHA * v.x;
        nac[4*q+1] = -ALPHA * v.y;
        nac[4*q+2] = -ALPHA * v.z;
        nac[4*q+3] = -ALPHA * v.w;
        snac += nac[4*q+0] + nac[4*q+1] + nac[4*q+2] + nac[4*q+3];
    }
}

/* ---------------- Pass 1: bracketed convergence search (fixed assignment) ---
   Simple static row-per-thread structure: keeps t[]/nac[] register-resident
   (R12 showed dynamic reassignment causes local-memory spills, ~4x slower).
   Tail: block-aggregated histogram folded in (removes the dys_hist kernel). */
__global__ void __launch_bounds__(TPB)
dys_pass1(const float* __restrict__ cost,
          const float* __restrict__ Avec,
          const float* __restrict__ bvec,
          const float* __restrict__ Vvec,
          const float* __restrict__ UT,
          const float* __restrict__ s_inv)
{
    __shared__ float4 sbuf[TPB * 16];     /* 32 KB: per-thread checkpoint state */
    __shared__ int    sh_cnt[NBKT];
    const int row = blockIdx.x * TPB + threadIdx.x;
    const int tid = threadIdx.x;

    if (tid < NBKT) sh_cnt[tid] = 0;

    const float bs = bvec[0];
    const float A0 = Avec[0];
    const float gg = UT[0] * s_inv[0] * Vvec[0];

    float t[NDIM], nac[NDIM], snac;
    load_nac(cost, row, nac, snac);

    float st = 0.0f;
#pragma unroll
    for (int j = 0; j < NDIM; j++) {
        t[j] = rng_u01((unsigned)(row * NDIM + j));
        st += t[j];
    }
    float negh = 0.0f;

    int   kbr = MAXIT + 1;                /* 201 = "no converged checkpoint"  */
    float nck = 0.0f, stck = 0.0f;

#pragma unroll 1
    for (int g = 0; g < NGRP; g++) {
        /* checkpoint: save state at k = 8g (swizzled, conflict-free STS.128) */
#pragma unroll
        for (int s2 = 0; s2 < 16; s2++) {
            int idx = (tid << 4) + ((s2 + tid) & 15);
            sbuf[idx] = make_float4(t[4*s2+0], t[4*s2+1], t[4*s2+2], t[4*s2+3]);
        }
        nck = negh; stck = st;

#pragma unroll 1
        for (int j = 0; j < CKPT - 1; j++)
            cheap_iter(t, nac, st, negh, snac, A0, bs, gg);
        float d2 = inst_iter(t, nac, st, negh, snac, A0, bs, gg);
        if (d2 <= TOL2) { kbr = (g + 1) * CKPT; break; }
    }

    if (kbr <= MAXIT) {
        /* save state at kbr - CKPT (from smem checkpoint) */
        float4* ts4 = (float4*)(g_tsave + (size_t)row * NDIM);
#pragma unroll
        for (int s2 = 0; s2 < 16; s2++)
            ts4[s2] = sbuf[(tid << 4) + ((s2 + tid) & 15)];
        g_negh[row] = nck;
        g_st[row]   = stck;
        g_ks[row]   = kbr - CKPT;
    } else {
        /* never converged: save state at 200 (catch-up will be zero iters)  */
        float4* ts4 = (float4*)(g_tsave + (size_t)row * NDIM);
#pragma unroll
        for (int s2 = 0; s2 < 16; s2++)
            ts4[s2] = make_float4(t[4*s2+0], t[4*s2+1], t[4*s2+2], t[4*s2+3]);
        g_negh[row] = negh;
        g_st[row]   = st;
        g_ks[row]   = MAXIT;
    }
    g_kbr[row] = kbr;

    /* folded block-aggregated histogram */
    int bkt = (kbr <= MAXIT) ? (kbr / CKPT - 1) : (NBKT - 1);
    __syncthreads();                      /* sh_cnt init visible               */
    atomicAdd(&sh_cnt[bkt], 1);

    int wmax = __reduce_max_sync(0xffffffffu, kbr);
    if ((tid & 31) == 0) atomicMax(&g_ctl[0], wmax);

    __syncthreads();
    if (tid < NBKT) {
        int c = sh_cnt[tid];
        if (c > 0) atomicAdd(&g_hist[tid], c);
    }
}

/* ------------- Refine: exact K from rows in the top bracket ----------------- */
__global__ void __launch_bounds__(TPB)
dys_refine(const float* __restrict__ cost,
           const float* __restrict__ Avec,
           const float* __restrict__ bvec,
           const float* __restrict__ Vvec,
           const float* __restrict__ UT,
           const float* __restrict__ s_inv)
{
    const int row = blockIdx.x * TPB + threadIdx.x;
    const int Kc  = g_ctl[0];

    if (Kc > MAXIT) {                     /* some row never converged -> cap  */
        if (row == 0) g_ctl[1] = MAXIT;
        return;
    }
    if (g_kbr[row] != Kc) return;         /* only top-bracket rows refine     */

    const float bs = bvec[0];
    const float A0 = Avec[0];
    const float gg = UT[0] * s_inv[0] * Vvec[0];

    float t[NDIM], nac[NDIM], snac;
    load_nac(cost, row, nac, snac);

    const float4* ts4 = (const float4*)(g_tsave + (size_t)row * NDIM);
#pragma unroll
    for (int q = 0; q < NDIM / 4; q++) {
        float4 v = ts4[q];
        t[4*q+0] = v.x; t[4*q+1] = v.y; t[4*q+2] = v.z; t[4*q+3] = v.w;
    }
    float negh = g_negh[row];
    float st   = g_st[row];
    const int ks = g_ks[row];             /* = Kc - CKPT                      */

    int kx = Kc;
#pragma unroll 1
    for (int j = 1; j <= CKPT; j++) {
        float d2 = inst_iter(t, nac, st, negh, snac, A0, bs, gg);
        if (d2 <= TOL2) { kx = ks + j; break; }   /* guaranteed by j=CKPT     */
    }
    atomicMax(&g_ctl[1], kx);
}

/* ------------- Prefix: warp-parallel exclusive scan over 26 buckets --------- */
__global__ void dys_prefix()
{
    const int i = threadIdx.x;            /* 32 threads */
    int v = (i < NBKT) ? g_hist[i] : 0;
    int s = v;
#pragma unroll
    for (int off = 1; off < 32; off <<= 1) {
        int n = __shfl_up_sync(0xffffffffu, s, off);
        if (i >= off) s += n;
    }
    if (i < NBKT) g_boff[i] = s - v;      /* exclusive prefix */
}

/* ------------- Scatter: per-block aggregation, low-contention atomics ------- */
__global__ void __launch_bounds__(256)
dys_scatter()
{
    __shared__ int sh_cnt[NBKT];
    __shared__ int sh_base[NBKT];
    const int tid = threadIdx.x;
    const int row = blockIdx.x * 256 + tid;

    if (tid < NBKT) sh_cnt[tid] = 0;
    __syncthreads();

    int kbr = g_kbr[row];
    int bkt = (kbr <= MAXIT) ? (kbr / CKPT - 1) : (NBKT - 1);
    int lrank = atomicAdd(&sh_cnt[bkt], 1);
    __syncthreads();

    if (tid < NBKT) {
        int c = sh_cnt[tid];
        sh_base[tid] = (c > 0) ? atomicAdd(&g_boff[tid], c) : 0;
    }
    __syncthreads();

    g_perm[sh_base[bkt] + lrank] = row;
}

/* ---------------- Pass 2: catch up to exact K, final step, output ----------- */
__global__ void __launch_bounds__(TPB)
dys_pass2(const float* __restrict__ cost,
          const float* __restrict__ Avec,
          const float* __restrict__ bvec,
          const float* __restrict__ Vvec,
          const float* __restrict__ UT,
          const float* __restrict__ s_inv,
          float* __restrict__ out)
{
    const int slot = blockIdx.x * TPB + threadIdx.x;
    const int row  = g_perm[slot];        /* lanes share a ks bucket -> no divergence */

    const float bs = bvec[0];
    const float A0 = Avec[0];
    const float gg = UT[0] * s_inv[0] * Vvec[0];

    float t[NDIM], nac[NDIM], snac;
    load_nac(cost, row, nac, snac);

    const float4* ts4 = (const float4*)(g_tsave + (size_t)row * NDIM);
#pragma unroll
    for (int q = 0; q < NDIM / 4; q++) {
        float4 v = ts4[q];
        t[4*q+0] = v.x; t[4*q+1] = v.y; t[4*q+2] = v.z; t[4*q+3] = v.w;
    }
    float negh = g_negh[row];
    float st   = g_st[row];
    const int ks = g_ks[row];
    const int K  = g_ctl[1];

#pragma unroll 1
    for (int k = ks; k < K; k++)
        cheap_iter(t, nac, st, negh, snac, A0, bs, gg);

    /* one final (differentiable) DYS step; sol = clip(t_new - h, 0, 1) */
    {
        float sx0 = 0.f, sx1 = 0.f, sx2 = 0.f, sx3 = 0.f;
#pragma unroll
        for (int j = 0; j < NDIM; j += 4) {
            float xa = add_sat01(t[j+0], negh);
            float xb = add_sat01(t[j+1], negh);
            float xc = add_sat01(t[j+2], negh);
            float xd = add_sat01(t[j+3], negh);
            sx0 += xa; sx1 += xb; sx2 += xc; sx3 += xd;
            t[j+0] = fmaf(xa, BETA, nac[j+0]);
            t[j+1] = fmaf(xb, BETA, nac[j+1]);
            t[j+2] = fmaf(xc, BETA, nac[j+2]);
            t[j+3] = fmaf(xd, BETA, nac[j+3]);
        }
        float sx = (sx0 + sx1) + (sx2 + sx3);
        float st_new = fmaf(BETA, sx, snac);
        float s  = sx + st_new - st - 64.0f * negh;
        float h  = fmaf(A0, s, -bs) * gg;
        float nh = -h;

        float4* o4 = (float4*)(out + (size_t)row * NDIM);
#pragma unroll
        for (int q = 0; q < NDIM / 4; q++) {
            float4 v;
            v.x = add_sat01(t[4*q+0], nh);
            v.y = add_sat01(t[4*q+1], nh);
            v.z = add_sat01(t[4*q+2], nh);
            v.w = add_sat01(t[4*q+3], nh);
            o4[q] = v;
        }
    }
}

extern "C" void kernel_launch(void* const* d_in, const int* in_sizes, int n_in,
                              void* d_out, int out_size)
{
    const float* cost  = (const float*)d_in[0];
    const float* A     = (const float*)d_in[1];
    const float* b     = (const float*)d_in[2];
    /* d_in[3] = lb (zeros), d_in[4] = ub (ones): folded into .sat clamp */
    const float* V     = (const float*)d_in[5];
    const float* UT    = (const float*)d_in[6];
    const float* s_inv = (const float*)d_in[7];
    float* out = (float*)d_out;

    void* ctlAddr = nullptr;
    cudaGetSymbolAddress(&ctlAddr, g_ctl);
    cudaMemsetAsync(ctlAddr, 0, 2 * sizeof(int));
    void* histAddr = nullptr;
    cudaGetSymbolAddress(&histAddr, g_hist);
    cudaMemsetAsync(histAddr, 0, NBKT * sizeof(int));

    dys_pass1  <<<NBLK, TPB>>>(cost, A, b, V, UT, s_inv);
    dys_refine <<<NBLK, TPB>>>(cost, A, b, V, UT, s_inv);
    dys_prefix <<<1, 32>>>();
    dys_scatter<<<BATCH / 256, 256>>>();
    dys_pass2  <<<NBLK, TPB>>>(cost, A, b, V, UT, s_inv, out);
}